// round 4
// baseline (speedup 1.0000x reference)
#include <cuda_runtime.h>
#include <math.h>
#include <stdint.h>

#define S_LEN 2048
#define HID   2560
#define NH    32
#define NKV   8
#define HD    128
#define QDIM  (NH*HD)    // 4096
#define KVDIM (NKV*HD)   // 1024

// Scratch (static device arrays; no allocation allowed)
__device__ float g_Q [S_LEN*QDIM];
__device__ float g_K [S_LEN*KVDIM];
__device__ float g_V [S_LEN*KVDIM];
__device__ float g_AO[S_LEN*QDIM];

// ---------------------------------------------------------------------------
// TF32 tensor-core GEMM NT: C[M,N] = A[M,K] * B[N,K]^T
// BM=BN=128, BK=16, 256 threads (8 warps, 2x4), warp tile 64x32.
// ---------------------------------------------------------------------------
__device__ __forceinline__ uint32_t f2tf(float x) {
    uint32_t y;
    asm("cvt.rna.tf32.f32 %0, %1;" : "=r"(y) : "f"(x));
    return y;
}

__device__ __forceinline__ void mma_tf32(float* d, const uint32_t* a, const uint32_t* b) {
    asm volatile(
        "mma.sync.aligned.m16n8k8.row.col.f32.tf32.tf32.f32 "
        "{%0,%1,%2,%3}, {%4,%5,%6,%7}, {%8,%9}, {%0,%1,%2,%3};\n"
        : "+f"(d[0]), "+f"(d[1]), "+f"(d[2]), "+f"(d[3])
        : "r"(a[0]), "r"(a[1]), "r"(a[2]), "r"(a[3]), "r"(b[0]), "r"(b[1]));
}

#define SMS 20  // smem row stride in words

__global__ void __launch_bounds__(256, 2) tf32_gemm_nt(const float* __restrict__ A,
                                                       const float* __restrict__ B,
                                                       float* __restrict__ C,
                                                       int M, int N, int Kd) {
    __shared__ uint32_t As[128 * SMS];
    __shared__ uint32_t Bs[128 * SMS];

    const int tid  = threadIdx.x;
    const int wid  = tid >> 5;
    const int lane = tid & 31;
    const int wm   = (wid & 1) * 64;
    const int wn   = (wid >> 1) * 32;
    const int g    = lane >> 2;
    const int c    = lane & 3;

    const int sr = tid >> 2;
    const int sc = (tid & 3) * 4;
    const float* Ap = A + (size_t)(blockIdx.y * 128 + sr) * Kd + sc;
    const float* Bp = B + (size_t)(blockIdx.x * 128 + sr) * Kd + sc;

    float acc[4][4][4];
#pragma unroll
    for (int i = 0; i < 4; i++)
#pragma unroll
        for (int j = 0; j < 4; j++)
#pragma unroll
            for (int k = 0; k < 4; k++) acc[i][j][k] = 0.f;

    float4 ra0 = *(const float4*)(Ap);
    float4 ra1 = *(const float4*)(Ap + (size_t)64 * Kd);
    float4 rb0 = *(const float4*)(Bp);
    float4 rb1 = *(const float4*)(Bp + (size_t)64 * Kd);

    for (int k0 = 0; k0 < Kd; k0 += 16) {
        uint4 u;
        u.x = f2tf(ra0.x); u.y = f2tf(ra0.y); u.z = f2tf(ra0.z); u.w = f2tf(ra0.w);
        *(uint4*)&As[sr * SMS + sc] = u;
        u.x = f2tf(ra1.x); u.y = f2tf(ra1.y); u.z = f2tf(ra1.z); u.w = f2tf(ra1.w);
        *(uint4*)&As[(sr + 64) * SMS + sc] = u;
        u.x = f2tf(rb0.x); u.y = f2tf(rb0.y); u.z = f2tf(rb0.z); u.w = f2tf(rb0.w);
        *(uint4*)&Bs[sr * SMS + sc] = u;
        u.x = f2tf(rb1.x); u.y = f2tf(rb1.y); u.z = f2tf(rb1.z); u.w = f2tf(rb1.w);
        *(uint4*)&Bs[(sr + 64) * SMS + sc] = u;
        __syncthreads();

        if (k0 + 16 < Kd) {
            ra0 = *(const float4*)(Ap + k0 + 16);
            ra1 = *(const float4*)(Ap + (size_t)64 * Kd + k0 + 16);
            rb0 = *(const float4*)(Bp + k0 + 16);
            rb1 = *(const float4*)(Bp + (size_t)64 * Kd + k0 + 16);
        }

#pragma unroll
        for (int kk = 0; kk < 16; kk += 8) {
            uint32_t af[4][4], bf[4][2];
#pragma unroll
            for (int mt = 0; mt < 4; mt++) {
                int r0 = wm + mt * 16 + g;
                af[mt][0] = As[r0 * SMS + kk + c];
                af[mt][1] = As[(r0 + 8) * SMS + kk + c];
                af[mt][2] = As[r0 * SMS + kk + c + 4];
                af[mt][3] = As[(r0 + 8) * SMS + kk + c + 4];
            }
#pragma unroll
            for (int nt = 0; nt < 4; nt++) {
                int n0 = wn + nt * 8 + g;
                bf[nt][0] = Bs[n0 * SMS + kk + c];
                bf[nt][1] = Bs[n0 * SMS + kk + c + 4];
            }
#pragma unroll
            for (int mt = 0; mt < 4; mt++)
#pragma unroll
                for (int nt = 0; nt < 4; nt++)
                    mma_tf32(acc[mt][nt], af[mt], bf[nt]);
        }
        __syncthreads();
    }

#pragma unroll
    for (int mt = 0; mt < 4; mt++) {
#pragma unroll
        for (int nt = 0; nt < 4; nt++) {
            int row = blockIdx.y * 128 + wm + mt * 16 + g;
            int col = blockIdx.x * 128 + wn + nt * 8 + c * 2;
            float2 v0 = {acc[mt][nt][0], acc[mt][nt][1]};
            float2 v1 = {acc[mt][nt][2], acc[mt][nt][3]};
            *(float2*)(C + (size_t)row * N + col)       = v0;
            *(float2*)(C + (size_t)(row + 8) * N + col) = v1;
        }
    }
}

// ---------------------------------------------------------------------------
// Fused per-head RMSNorm + RoPE, in-place on X[S, nheads*128].
// ---------------------------------------------------------------------------
__global__ void rms_rope_kernel(float* __restrict__ X, const float* __restrict__ w,
                                const float* __restrict__ cosp, const float* __restrict__ sinp,
                                int nheads, int nrows) {
    int warp = (blockIdx.x * blockDim.x + threadIdx.x) >> 5;
    int lane = threadIdx.x & 31;
    if (warp >= nrows) return;
    int s = warp / nheads;

    float* p = X + (size_t)warp * HD;
    float4 x = *(float4*)(p + lane * 4);

    float ss = x.x * x.x + x.y * x.y + x.z * x.z + x.w * x.w;
#pragma unroll
    for (int o = 16; o; o >>= 1) ss += __shfl_xor_sync(0xffffffffu, ss, o);
    float r = rsqrtf(ss * (1.0f / HD) + 1e-6f);

    float4 wv = *(const float4*)(w + lane * 4);
    x.x *= r * wv.x; x.y *= r * wv.y; x.z *= r * wv.z; x.w *= r * wv.w;

    float4 rot;
    rot.x = __shfl_xor_sync(0xffffffffu, x.x, 16);
    rot.y = __shfl_xor_sync(0xffffffffu, x.y, 16);
    rot.z = __shfl_xor_sync(0xffffffffu, x.z, 16);
    rot.w = __shfl_xor_sync(0xffffffffu, x.w, 16);
    float sgn = (lane < 16) ? -1.f : 1.f;

    float4 cv = *(const float4*)(cosp + (size_t)s * HD + lane * 4);
    float4 sv = *(const float4*)(sinp + (size_t)s * HD + lane * 4);

    float4 o;
    o.x = x.x * cv.x + sgn * rot.x * sv.x;
    o.y = x.y * cv.y + sgn * rot.y * sv.y;
    o.z = x.z * cv.z + sgn * rot.z * sv.z;
    o.w = x.w * cv.w + sgn * rot.w * sv.w;
    *(float4*)(p + lane * 4) = o;
}

// ---------------------------------------------------------------------------
// Causal GQA flash attention, lane-per-key x 8 query rows per warp.
// Block: 256 threads = 8 warps = 64 query rows of one head.
// K/V/Q tiles (64 rows x 128, stride 132) in dynamic smem (~99KB).
// ---------------------------------------------------------------------------
#define FP 132  // padded row stride in floats

__global__ void __launch_bounds__(256, 2) flash_kernel(const float* __restrict__ Q,
                                                       const float* __restrict__ K,
                                                       const float* __restrict__ V,
                                                       float* __restrict__ O) {
    extern __shared__ float sm[];
    float* Qs = sm;                 // [64][FP]
    float* Ks = sm + 64 * FP;       // [64][FP]
    float* Vs = sm + 2 * 64 * FP;   // [64][FP]

    const int tid  = threadIdx.x;
    const int w    = tid >> 5;
    const int lane = tid & 31;
    const int h    = blockIdx.y;
    const int kvh  = h >> 2;
    const int base = blockIdx.x * 64;
    const float scale = 0.08838834764831845f;  // 1/sqrt(128)

    // stage Q tile (64 rows of this head)
    {
        const int r  = tid >> 2;
        const int c0 = (tid & 3) * 8;
        const float* src = Q + (size_t)(base + r) * QDIM + h * HD;
#pragma unroll
        for (int i = 0; i < 8; i++)
            *(float4*)&Qs[r * FP + (c0 + i) * 4] = *(const float4*)(src + (c0 + i) * 4);
    }

    float4 acc[8];
    float m[8], l[8];
#pragma unroll
    for (int r = 0; r < 8; r++) {
        acc[r] = make_float4(0.f, 0.f, 0.f, 0.f);
        m[r] = -1e30f; l[r] = 0.f;
    }

    const int wrow0 = base + w * 8;   // first query row of this warp
    const int wmax  = wrow0 + 7;
    const float* qb = &Qs[(w * 8) * FP];

    for (int kb = 0; kb <= base + 63; kb += 64) {
        __syncthreads();   // prev-iter compute done (and Q staging before first K/V use)
        {
            const int r  = tid >> 2;
            const int c0 = (tid & 3) * 8;
            const float* ksrc = K + (size_t)(kb + r) * KVDIM + kvh * HD;
            const float* vsrc = V + (size_t)(kb + r) * KVDIM + kvh * HD;
#pragma unroll
            for (int i = 0; i < 8; i++) {
                *(float4*)&Ks[r * FP + (c0 + i) * 4] = *(const float4*)(ksrc + (c0 + i) * 4);
                *(float4*)&Vs[r * FP + (c0 + i) * 4] = *(const float4*)(vsrc + (c0 + i) * 4);
            }
        }
        __syncthreads();

        if (kb <= wmax) {
#pragma unroll
            for (int sub = 0; sub < 2; sub++) {
                if (kb + sub * 32 > wmax) break;   // whole subtile beyond causal bound
                const int j = sub * 32 + lane;     // key index in tile (lane-parallel)
                const int g = kb + j;              // global key index

                // ---- scores: 32 keys x 8 rows ----
                float sc[8];
#pragma unroll
                for (int r = 0; r < 8; r++) sc[r] = 0.f;
                const float* kr = &Ks[j * FP];
#pragma unroll
                for (int d4 = 0; d4 < 32; d4++) {
                    float4 k4 = *(const float4*)(kr + d4 * 4);
#pragma unroll
                    for (int r = 0; r < 8; r++) {
                        float4 q4 = *(const float4*)(qb + r * FP + d4 * 4);
                        sc[r] = fmaf(q4.x, k4.x,
                                fmaf(q4.y, k4.y,
                                fmaf(q4.z, k4.z,
                                fmaf(q4.w, k4.w, sc[r]))));
                    }
                }

                // ---- online softmax per row ----
                float p[8];
#pragma unroll
                for (int r = 0; r < 8; r++) {
                    const int row = wrow0 + r;
                    const bool valid = (g <= row);
                    float s = valid ? sc[r] * scale : -1e30f;
                    float mx = s;
#pragma unroll
                    for (int o = 16; o; o >>= 1)
                        mx = fmaxf(mx, __shfl_xor_sync(0xffffffffu, mx, o));
                    float mn = fmaxf(m[r], mx);
                    float corr = __expf(m[r] - mn);
                    p[r] = valid ? __expf(s - mn) : 0.f;
                    l[r] = l[r] * corr + p[r];   // per-lane partial sum
                    acc[r].x *= corr; acc[r].y *= corr;
                    acc[r].z *= corr; acc[r].w *= corr;
                    m[r] = mn;
                }

                // ---- PV accumulation ----
#pragma unroll
                for (int j2 = 0; j2 < 32; j2++) {
                    float4 v4 = *(const float4*)(&Vs[(sub * 32 + j2) * FP + lane * 4]);
#pragma unroll
                    for (int r = 0; r < 8; r++) {
                        float pj = __shfl_sync(0xffffffffu, p[r], j2);
                        acc[r].x = fmaf(pj, v4.x, acc[r].x);
                        acc[r].y = fmaf(pj, v4.y, acc[r].y);
                        acc[r].z = fmaf(pj, v4.z, acc[r].z);
                        acc[r].w = fmaf(pj, v4.w, acc[r].w);
                    }
                }
            }
        }
    }

    // epilogue: reduce l across lanes, normalize, store
#pragma unroll
    for (int r = 0; r < 8; r++) {
        float lt = l[r];
#pragma unroll
        for (int o = 16; o; o >>= 1) lt += __shfl_xor_sync(0xffffffffu, lt, o);
        float inv = 1.f / lt;
        float4 o4 = {acc[r].x * inv, acc[r].y * inv, acc[r].z * inv, acc[r].w * inv};
        *(float4*)(O + (size_t)(wrow0 + r) * QDIM + h * HD + lane * 4) = o4;
    }
}

// ---------------------------------------------------------------------------
extern "C" void kernel_launch(void* const* d_in, const int* in_sizes, int n_in,
                              void* d_out, int out_size) {
    const float* X    = (const float*)d_in[0];
    const float* cosp = (const float*)d_in[1];
    const float* sinp = (const float*)d_in[2];
    const float* Wq   = (const float*)d_in[3];
    const float* Wk   = (const float*)d_in[4];
    const float* Wv   = (const float*)d_in[5];
    const float* Wo   = (const float*)d_in[6];
    const float* qw   = (const float*)d_in[7];
    const float* kw   = (const float*)d_in[8];
    float* out = (float*)d_out;

    float *Q, *K, *V, *AO;
    cudaGetSymbolAddress((void**)&Q,  g_Q);
    cudaGetSymbolAddress((void**)&K,  g_K);
    cudaGetSymbolAddress((void**)&V,  g_V);
    cudaGetSymbolAddress((void**)&AO, g_AO);

    // Projections: C = X @ W^T  (TF32 tensor cores)
    tf32_gemm_nt<<<dim3(QDIM / 128,  S_LEN / 128), 256>>>(X, Wq, Q, S_LEN, QDIM,  HID);
    tf32_gemm_nt<<<dim3(KVDIM / 128, S_LEN / 128), 256>>>(X, Wk, K, S_LEN, KVDIM, HID);
    tf32_gemm_nt<<<dim3(KVDIM / 128, S_LEN / 128), 256>>>(X, Wv, V, S_LEN, KVDIM, HID);

    // RMSNorm + RoPE (in place)
    rms_rope_kernel<<<(S_LEN * NH)  / 8, 256>>>(Q, qw, cosp, sinp, NH,  S_LEN * NH);
    rms_rope_kernel<<<(S_LEN * NKV) / 8, 256>>>(K, kw, cosp, sinp, NKV, S_LEN * NKV);

    // Flash attention (lane-per-key, 8 rows/warp)
    int smem = 3 * 64 * FP * sizeof(float);  // ~99KB
    cudaFuncSetAttribute(flash_kernel, cudaFuncAttributeMaxDynamicSharedMemorySize, smem);
    flash_kernel<<<dim3(S_LEN / 64, NH), 256, smem>>>(Q, K, V, AO);

    // Output projection: out = AO @ Wo^T  (TF32 tensor cores)
    tf32_gemm_nt<<<dim3(HID / 128, S_LEN / 128), 256>>>(AO, Wo, out, S_LEN, HID, QDIM);
}

// round 7
// speedup vs baseline: 2.4078x; 2.4078x over previous
#include <cuda_runtime.h>
#include <math.h>
#include <stdint.h>

#define S_LEN 2048
#define HID   2560
#define NH    32
#define NKV   8
#define HD    128
#define QDIM  (NH*HD)    // 4096
#define KVDIM (NKV*HD)   // 1024

// Scratch (static device arrays; no allocation allowed)
__device__ float g_Q [S_LEN*QDIM];
__device__ float g_K [S_LEN*KVDIM];
__device__ float g_V [S_LEN*KVDIM];
__device__ float g_AO[S_LEN*QDIM];

// ---------------------------------------------------------------------------
// TF32 tensor-core GEMM NT: C[M,N] = A[M,K] * B[N,K]^T
// BM=BN=128, BK=16, 256 threads (8 warps, 2x4), warp tile 64x32.
// Double-buffered smem (ping-pong), one sync per K-tile.
// ---------------------------------------------------------------------------
__device__ __forceinline__ uint32_t f2tf(float x) {
    uint32_t y;
    asm("cvt.rna.tf32.f32 %0, %1;" : "=r"(y) : "f"(x));
    return y;
}

__device__ __forceinline__ void mma_tf32(float* d, const uint32_t* a, const uint32_t* b) {
    asm volatile(
        "mma.sync.aligned.m16n8k8.row.col.f32.tf32.tf32.f32 "
        "{%0,%1,%2,%3}, {%4,%5,%6,%7}, {%8,%9}, {%0,%1,%2,%3};\n"
        : "+f"(d[0]), "+f"(d[1]), "+f"(d[2]), "+f"(d[3])
        : "r"(a[0]), "r"(a[1]), "r"(a[2]), "r"(a[3]), "r"(b[0]), "r"(b[1]));
}

#define SMS 20  // smem row stride in words

__global__ void __launch_bounds__(256, 2) tf32_gemm_nt(const float* __restrict__ A,
                                                       const float* __restrict__ B,
                                                       float* __restrict__ C,
                                                       int M, int N, int Kd) {
    __shared__ uint32_t As[2][128 * SMS];
    __shared__ uint32_t Bs[2][128 * SMS];

    const int tid  = threadIdx.x;
    const int wid  = tid >> 5;
    const int lane = tid & 31;
    const int wm   = (wid & 1) * 64;
    const int wn   = (wid >> 1) * 32;
    const int g    = lane >> 2;
    const int c    = lane & 3;

    const int sr = tid >> 2;
    const int sc = (tid & 3) * 4;
    const float* Ap = A + (size_t)(blockIdx.y * 128 + sr) * Kd + sc;
    const float* Bp = B + (size_t)(blockIdx.x * 128 + sr) * Kd + sc;

    float acc[4][4][4];
#pragma unroll
    for (int i = 0; i < 4; i++)
#pragma unroll
        for (int j = 0; j < 4; j++)
#pragma unroll
            for (int k = 0; k < 4; k++) acc[i][j][k] = 0.f;

    float4 ra0 = *(const float4*)(Ap);
    float4 ra1 = *(const float4*)(Ap + (size_t)64 * Kd);
    float4 rb0 = *(const float4*)(Bp);
    float4 rb1 = *(const float4*)(Bp + (size_t)64 * Kd);

    // stage tile 0 into buffer 0
    {
        uint4 u;
        u.x = f2tf(ra0.x); u.y = f2tf(ra0.y); u.z = f2tf(ra0.z); u.w = f2tf(ra0.w);
        *(uint4*)&As[0][sr * SMS + sc] = u;
        u.x = f2tf(ra1.x); u.y = f2tf(ra1.y); u.z = f2tf(ra1.z); u.w = f2tf(ra1.w);
        *(uint4*)&As[0][(sr + 64) * SMS + sc] = u;
        u.x = f2tf(rb0.x); u.y = f2tf(rb0.y); u.z = f2tf(rb0.z); u.w = f2tf(rb0.w);
        *(uint4*)&Bs[0][sr * SMS + sc] = u;
        u.x = f2tf(rb1.x); u.y = f2tf(rb1.y); u.z = f2tf(rb1.z); u.w = f2tf(rb1.w);
        *(uint4*)&Bs[0][(sr + 64) * SMS + sc] = u;
    }
    __syncthreads();

    int cur = 0;
    for (int k0 = 0; k0 < Kd; k0 += 16) {
        const bool has_next = (k0 + 16 < Kd);
        if (has_next) {
            ra0 = *(const float4*)(Ap + k0 + 16);
            ra1 = *(const float4*)(Ap + (size_t)64 * Kd + k0 + 16);
            rb0 = *(const float4*)(Bp + k0 + 16);
            rb1 = *(const float4*)(Bp + (size_t)64 * Kd + k0 + 16);
        }

        const uint32_t* Ab = As[cur];
        const uint32_t* Bb = Bs[cur];
#pragma unroll
        for (int kk = 0; kk < 16; kk += 8) {
            uint32_t af[4][4], bf[4][2];
#pragma unroll
            for (int mt = 0; mt < 4; mt++) {
                int r0 = wm + mt * 16 + g;
                af[mt][0] = Ab[r0 * SMS + kk + c];
                af[mt][1] = Ab[(r0 + 8) * SMS + kk + c];
                af[mt][2] = Ab[r0 * SMS + kk + c + 4];
                af[mt][3] = Ab[(r0 + 8) * SMS + kk + c + 4];
            }
#pragma unroll
            for (int nt = 0; nt < 4; nt++) {
                int n0 = wn + nt * 8 + g;
                bf[nt][0] = Bb[n0 * SMS + kk + c];
                bf[nt][1] = Bb[n0 * SMS + kk + c + 4];
            }
#pragma unroll
            for (int mt = 0; mt < 4; mt++)
#pragma unroll
                for (int nt = 0; nt < 4; nt++)
                    mma_tf32(acc[mt][nt], af[mt], bf[nt]);
        }

        if (has_next) {
            uint32_t* An = As[cur ^ 1];
            uint32_t* Bn = Bs[cur ^ 1];
            uint4 u;
            u.x = f2tf(ra0.x); u.y = f2tf(ra0.y); u.z = f2tf(ra0.z); u.w = f2tf(ra0.w);
            *(uint4*)&An[sr * SMS + sc] = u;
            u.x = f2tf(ra1.x); u.y = f2tf(ra1.y); u.z = f2tf(ra1.z); u.w = f2tf(ra1.w);
            *(uint4*)&An[(sr + 64) * SMS + sc] = u;
            u.x = f2tf(rb0.x); u.y = f2tf(rb0.y); u.z = f2tf(rb0.z); u.w = f2tf(rb0.w);
            *(uint4*)&Bn[sr * SMS + sc] = u;
            u.x = f2tf(rb1.x); u.y = f2tf(rb1.y); u.z = f2tf(rb1.z); u.w = f2tf(rb1.w);
            *(uint4*)&Bn[(sr + 64) * SMS + sc] = u;
            __syncthreads();
            cur ^= 1;
        }
    }

#pragma unroll
    for (int mt = 0; mt < 4; mt++) {
#pragma unroll
        for (int nt = 0; nt < 4; nt++) {
            int row = blockIdx.y * 128 + wm + mt * 16 + g;
            int col = blockIdx.x * 128 + wn + nt * 8 + c * 2;
            float2 v0 = {acc[mt][nt][0], acc[mt][nt][1]};
            float2 v1 = {acc[mt][nt][2], acc[mt][nt][3]};
            *(float2*)(C + (size_t)row * N + col)       = v0;
            *(float2*)(C + (size_t)(row + 8) * N + col) = v1;
        }
    }
}

// ---------------------------------------------------------------------------
// Merged per-head RMSNorm + RoPE over BOTH Q and K, in-place.
// One warp per (s, head) row; rotate_half via shfl_xor(16).
// ---------------------------------------------------------------------------
__global__ void rms_rope_all(float* __restrict__ Qx, float* __restrict__ Kx,
                             const float* __restrict__ qw, const float* __restrict__ kw,
                             const float* __restrict__ cosp, const float* __restrict__ sinp) {
    const int NQ = S_LEN * NH;
    int warp = (blockIdx.x * blockDim.x + threadIdx.x) >> 5;
    int lane = threadIdx.x & 31;

    float* p;
    const float* w;
    int s;
    if (warp < NQ) {
        p = Qx + (size_t)warp * HD;
        w = qw;
        s = warp / NH;
    } else {
        int t = warp - NQ;
        p = Kx + (size_t)t * HD;
        w = kw;
        s = t / NKV;
    }

    float4 x = *(float4*)(p + lane * 4);

    float ss = x.x * x.x + x.y * x.y + x.z * x.z + x.w * x.w;
#pragma unroll
    for (int o = 16; o; o >>= 1) ss += __shfl_xor_sync(0xffffffffu, ss, o);
    float r = rsqrtf(ss * (1.0f / HD) + 1e-6f);

    float4 wv = *(const float4*)(w + lane * 4);
    x.x *= r * wv.x; x.y *= r * wv.y; x.z *= r * wv.z; x.w *= r * wv.w;

    float4 rot;
    rot.x = __shfl_xor_sync(0xffffffffu, x.x, 16);
    rot.y = __shfl_xor_sync(0xffffffffu, x.y, 16);
    rot.z = __shfl_xor_sync(0xffffffffu, x.z, 16);
    rot.w = __shfl_xor_sync(0xffffffffu, x.w, 16);
    float sgn = (lane < 16) ? -1.f : 1.f;

    float4 cv = *(const float4*)(cosp + (size_t)s * HD + lane * 4);
    float4 sv = *(const float4*)(sinp + (size_t)s * HD + lane * 4);

    float4 o;
    o.x = x.x * cv.x + sgn * rot.x * sv.x;
    o.y = x.y * cv.y + sgn * rot.y * sv.y;
    o.z = x.z * cv.z + sgn * rot.z * sv.z;
    o.w = x.w * cv.w + sgn * rot.w * sv.w;
    *(float4*)(p + lane * 4) = o;
}

// ---------------------------------------------------------------------------
// Causal GQA flash attention, fixed-max softmax (scores bounded by 11.32 < 12
// since RMSNorm gives |q|=|k|=sqrt(128) and RoPE preserves norms).
// Block: 512 threads = 16 warps; each warp handles query rows base+w and
// base+w+16 (2 independent chains). K/V tiles of 64 keys in smem (64KB).
// ---------------------------------------------------------------------------
__global__ void __launch_bounds__(512) flash_kernel(const float* __restrict__ Q,
                                                    const float* __restrict__ K,
                                                    const float* __restrict__ V,
                                                    float* __restrict__ O) {
    extern __shared__ float sm[];
    float* Ks = sm;              // [64][128]
    float* Vs = sm + 64 * 128;   // [64][128]

    const int tid  = threadIdx.x;
    const int w    = tid >> 5;
    const int lane = tid & 31;
    const int h    = blockIdx.y;
    const int kvh  = h >> 2;
    const int base = blockIdx.x * 32;
    const int s0   = base + w;
    const int s1   = base + w + 16;
    const float scale = 0.08838834764831845f;  // 1/sqrt(128)
    const float FM = 12.0f;                    // fixed softmax max bound

    float4 qv0 = *(const float4*)(Q + (size_t)s0 * QDIM + h * HD + lane * 4);
    float4 qv1 = *(const float4*)(Q + (size_t)s1 * QDIM + h * HD + lane * 4);
    float4 acc0 = {0.f, 0.f, 0.f, 0.f};
    float4 acc1 = {0.f, 0.f, 0.f, 0.f};
    float l0 = 0.f, l1 = 0.f;

    for (int kb = 0; kb <= base + 31; kb += 64) {
#pragma unroll
        for (int i = 0; i < 4; i++) {
            int f = tid + i * 512;
            int r = f >> 5, c4 = (f & 31) * 4;
            *(float4*)(Ks + r * 128 + c4) =
                *(const float4*)(K + (size_t)(kb + r) * KVDIM + kvh * HD + c4);
            *(float4*)(Vs + r * 128 + c4) =
                *(const float4*)(V + (size_t)(kb + r) * KVDIM + kvh * HD + c4);
        }
        __syncthreads();

        int jlim0 = s0 - kb;                 // >= 0 always (kb <= base <= s0)
        int jmax1 = s1 - kb + 1;
        if (jmax1 > 64) jmax1 = 64;

        for (int j = 0; j < jmax1; j++) {
            float4 kv = *(const float4*)(Ks + j * 128 + lane * 4);
            float d0 = qv0.x * kv.x + qv0.y * kv.y + qv0.z * kv.z + qv0.w * kv.w;
            float d1 = qv1.x * kv.x + qv1.y * kv.y + qv1.z * kv.z + qv1.w * kv.w;
#pragma unroll
            for (int o = 16; o; o >>= 1) {
                d0 += __shfl_xor_sync(0xffffffffu, d0, o);
                d1 += __shfl_xor_sync(0xffffffffu, d1, o);
            }
            float p0 = (j <= jlim0) ? __expf(fmaf(d0, scale, -FM)) : 0.f;
            float p1 = __expf(fmaf(d1, scale, -FM));
            l0 += p0;
            l1 += p1;
            float4 vv = *(const float4*)(Vs + j * 128 + lane * 4);
            acc0.x = fmaf(p0, vv.x, acc0.x);
            acc0.y = fmaf(p0, vv.y, acc0.y);
            acc0.z = fmaf(p0, vv.z, acc0.z);
            acc0.w = fmaf(p0, vv.w, acc0.w);
            acc1.x = fmaf(p1, vv.x, acc1.x);
            acc1.y = fmaf(p1, vv.y, acc1.y);
            acc1.z = fmaf(p1, vv.z, acc1.z);
            acc1.w = fmaf(p1, vv.w, acc1.w);
        }
        __syncthreads();
    }

    float inv0 = 1.f / l0;
    float inv1 = 1.f / l1;
    float4 o0 = {acc0.x * inv0, acc0.y * inv0, acc0.z * inv0, acc0.w * inv0};
    float4 o1 = {acc1.x * inv1, acc1.y * inv1, acc1.z * inv1, acc1.w * inv1};
    *(float4*)(O + (size_t)s0 * QDIM + h * HD + lane * 4) = o0;
    *(float4*)(O + (size_t)s1 * QDIM + h * HD + lane * 4) = o1;
}

// ---------------------------------------------------------------------------
extern "C" void kernel_launch(void* const* d_in, const int* in_sizes, int n_in,
                              void* d_out, int out_size) {
    const float* X    = (const float*)d_in[0];
    const float* cosp = (const float*)d_in[1];
    const float* sinp = (const float*)d_in[2];
    const float* Wq   = (const float*)d_in[3];
    const float* Wk   = (const float*)d_in[4];
    const float* Wv   = (const float*)d_in[5];
    const float* Wo   = (const float*)d_in[6];
    const float* qw   = (const float*)d_in[7];
    const float* kw   = (const float*)d_in[8];
    float* out = (float*)d_out;

    float *Q, *K, *V, *AO;
    cudaGetSymbolAddress((void**)&Q,  g_Q);
    cudaGetSymbolAddress((void**)&K,  g_K);
    cudaGetSymbolAddress((void**)&V,  g_V);
    cudaGetSymbolAddress((void**)&AO, g_AO);

    // 0,1: Q and K projections
    tf32_gemm_nt<<<dim3(QDIM / 128,  S_LEN / 128), 256>>>(X, Wq, Q, S_LEN, QDIM,  HID);
    tf32_gemm_nt<<<dim3(KVDIM / 128, S_LEN / 128), 256>>>(X, Wk, K, S_LEN, KVDIM, HID);

    // 2: merged RMSNorm+RoPE on Q and K
    {
        int nwarps = S_LEN * NH + S_LEN * NKV;
        rms_rope_all<<<nwarps / 8, 256>>>(Q, K, qw, kw, cosp, sinp);
    }

    // 3: V projection
    tf32_gemm_nt<<<dim3(KVDIM / 128, S_LEN / 128), 256>>>(X, Wv, V, S_LEN, KVDIM, HID);

    // 4: flash attention
    int smem = 2 * 64 * 128 * sizeof(float);  // 64KB
    cudaFuncSetAttribute(flash_kernel, cudaFuncAttributeMaxDynamicSharedMemorySize, smem);
    flash_kernel<<<dim3(S_LEN / 32, NH), 512, smem>>>(Q, K, V, AO);

    // 5: output projection
    tf32_gemm_nt<<<dim3(HID / 128, S_LEN / 128), 256>>>(AO, Wo, out, S_LEN, HID, QDIM);
}

// round 9
// speedup vs baseline: 4.6301x; 1.9230x over previous
#include <cuda_runtime.h>
#include <math.h>
#include <stdint.h>

#define S_LEN 2048
#define HID   2560
#define NH    32
#define NKV   8
#define HD    128
#define QDIM  (NH*HD)    // 4096
#define KVDIM (NKV*HD)   // 1024

// Scratch (static device arrays; no allocation allowed)
__device__ float g_Q [S_LEN*QDIM];
__device__ float g_K [S_LEN*KVDIM];
__device__ float g_V [S_LEN*KVDIM];
__device__ float g_AO[S_LEN*QDIM];

// ---------------------------------------------------------------------------
// helpers
// ---------------------------------------------------------------------------
__device__ __forceinline__ uint32_t f2tf(float x) {
    uint32_t y;
    asm("cvt.rna.tf32.f32 %0, %1;" : "=r"(y) : "f"(x));
    return y;
}

__device__ __forceinline__ void mma_tf32(float* d, const uint32_t* a, const uint32_t* b) {
    asm volatile(
        "mma.sync.aligned.m16n8k8.row.col.f32.tf32.tf32.f32 "
        "{%0,%1,%2,%3}, {%4,%5,%6,%7}, {%8,%9}, {%0,%1,%2,%3};\n"
        : "+f"(d[0]), "+f"(d[1]), "+f"(d[2]), "+f"(d[3])
        : "r"(a[0]), "r"(a[1]), "r"(a[2]), "r"(a[3]), "r"(b[0]), "r"(b[1]));
}

// ---------------------------------------------------------------------------
// TF32 tensor-core GEMM NT body: C[M,N] = A[M,K] * B[N,K]^T
// BM=BN=128, BK=16, 256 threads (8 warps, 2x4), warp tile 64x32.
// Double-buffered smem (ping-pong), one sync per K-tile.
// ---------------------------------------------------------------------------
#define SMS 20  // smem row stride in words

__device__ __forceinline__ void gemm_body(const float* __restrict__ A,
                                          const float* __restrict__ B,
                                          float* __restrict__ C,
                                          int N, int Kd, int bx, int by,
                                          uint32_t* As, uint32_t* Bs) {
    const int tid  = threadIdx.x;
    const int wid  = tid >> 5;
    const int lane = tid & 31;
    const int wm   = (wid & 1) * 64;
    const int wn   = (wid >> 1) * 32;
    const int g    = lane >> 2;
    const int c    = lane & 3;

    const int sr = tid >> 2;
    const int sc = (tid & 3) * 4;
    const float* Ap = A + (size_t)(by * 128 + sr) * Kd + sc;
    const float* Bp = B + (size_t)(bx * 128 + sr) * Kd + sc;

    float acc[4][4][4];
#pragma unroll
    for (int i = 0; i < 4; i++)
#pragma unroll
        for (int j = 0; j < 4; j++)
#pragma unroll
            for (int k = 0; k < 4; k++) acc[i][j][k] = 0.f;

    float4 ra0 = *(const float4*)(Ap);
    float4 ra1 = *(const float4*)(Ap + (size_t)64 * Kd);
    float4 rb0 = *(const float4*)(Bp);
    float4 rb1 = *(const float4*)(Bp + (size_t)64 * Kd);

    {
        uint4 u;
        u.x = f2tf(ra0.x); u.y = f2tf(ra0.y); u.z = f2tf(ra0.z); u.w = f2tf(ra0.w);
        *(uint4*)&As[sr * SMS + sc] = u;
        u.x = f2tf(ra1.x); u.y = f2tf(ra1.y); u.z = f2tf(ra1.z); u.w = f2tf(ra1.w);
        *(uint4*)&As[(sr + 64) * SMS + sc] = u;
        u.x = f2tf(rb0.x); u.y = f2tf(rb0.y); u.z = f2tf(rb0.z); u.w = f2tf(rb0.w);
        *(uint4*)&Bs[sr * SMS + sc] = u;
        u.x = f2tf(rb1.x); u.y = f2tf(rb1.y); u.z = f2tf(rb1.z); u.w = f2tf(rb1.w);
        *(uint4*)&Bs[(sr + 64) * SMS + sc] = u;
    }
    __syncthreads();

    int cur = 0;
    for (int k0 = 0; k0 < Kd; k0 += 16) {
        const bool has_next = (k0 + 16 < Kd);
        if (has_next) {
            ra0 = *(const float4*)(Ap + k0 + 16);
            ra1 = *(const float4*)(Ap + (size_t)64 * Kd + k0 + 16);
            rb0 = *(const float4*)(Bp + k0 + 16);
            rb1 = *(const float4*)(Bp + (size_t)64 * Kd + k0 + 16);
        }

        const uint32_t* Ab = As + cur * (128 * SMS * 2);
        const uint32_t* Bb = Bs + cur * (128 * SMS * 2);
#pragma unroll
        for (int kk = 0; kk < 16; kk += 8) {
            uint32_t af[4][4], bf[4][2];
#pragma unroll
            for (int mt = 0; mt < 4; mt++) {
                int r0 = wm + mt * 16 + g;
                af[mt][0] = Ab[r0 * SMS + kk + c];
                af[mt][1] = Ab[(r0 + 8) * SMS + kk + c];
                af[mt][2] = Ab[r0 * SMS + kk + c + 4];
                af[mt][3] = Ab[(r0 + 8) * SMS + kk + c + 4];
            }
#pragma unroll
            for (int nt = 0; nt < 4; nt++) {
                int n0 = wn + nt * 8 + g;
                bf[nt][0] = Bb[n0 * SMS + kk + c];
                bf[nt][1] = Bb[n0 * SMS + kk + c + 4];
            }
#pragma unroll
            for (int mt = 0; mt < 4; mt++)
#pragma unroll
                for (int nt = 0; nt < 4; nt++)
                    mma_tf32(acc[mt][nt], af[mt], bf[nt]);
        }

        if (has_next) {
            uint32_t* An = As + (cur ^ 1) * (128 * SMS * 2);
            uint32_t* Bn = Bs + (cur ^ 1) * (128 * SMS * 2);
            uint4 u;
            u.x = f2tf(ra0.x); u.y = f2tf(ra0.y); u.z = f2tf(ra0.z); u.w = f2tf(ra0.w);
            *(uint4*)&An[sr * SMS + sc] = u;
            u.x = f2tf(ra1.x); u.y = f2tf(ra1.y); u.z = f2tf(ra1.z); u.w = f2tf(ra1.w);
            *(uint4*)&An[(sr + 64) * SMS + sc] = u;
            u.x = f2tf(rb0.x); u.y = f2tf(rb0.y); u.z = f2tf(rb0.z); u.w = f2tf(rb0.w);
            *(uint4*)&Bn[sr * SMS + sc] = u;
            u.x = f2tf(rb1.x); u.y = f2tf(rb1.y); u.z = f2tf(rb1.z); u.w = f2tf(rb1.w);
            *(uint4*)&Bn[(sr + 64) * SMS + sc] = u;
            __syncthreads();
            cur ^= 1;
        }
    }

#pragma unroll
    for (int mt = 0; mt < 4; mt++) {
#pragma unroll
        for (int nt = 0; nt < 4; nt++) {
            int row = by * 128 + wm + mt * 16 + g;
            int col = bx * 128 + wn + nt * 8 + c * 2;
            float2 v0 = {acc[mt][nt][0], acc[mt][nt][1]};
            float2 v1 = {acc[mt][nt][2], acc[mt][nt][3]};
            *(float2*)(C + (size_t)row * N + col)       = v0;
            *(float2*)(C + (size_t)(row + 8) * N + col) = v1;
        }
    }
}

__global__ void __launch_bounds__(256, 2) tf32_gemm_nt(const float* __restrict__ A,
                                                       const float* __restrict__ B,
                                                       float* __restrict__ C,
                                                       int M, int N, int Kd) {
    __shared__ uint32_t As[2 * 128 * SMS * 2];
    __shared__ uint32_t Bs[2 * 128 * SMS * 2];
    gemm_body(A, B, C, N, Kd, blockIdx.x, blockIdx.y, As, Bs);
}

// K and V projections merged into one launch (blockIdx.z selects)
__global__ void __launch_bounds__(256, 2) tf32_gemm_kv(const float* __restrict__ A,
                                                       const float* __restrict__ B0,
                                                       const float* __restrict__ B1,
                                                       float* __restrict__ C0,
                                                       float* __restrict__ C1,
                                                       int N, int Kd) {
    __shared__ uint32_t As[2 * 128 * SMS * 2];
    __shared__ uint32_t Bs[2 * 128 * SMS * 2];
    const float* B = blockIdx.z ? B1 : B0;
    float* C = blockIdx.z ? C1 : C0;
    gemm_body(A, B, C, N, Kd, blockIdx.x, blockIdx.y, As, Bs);
}

// ---------------------------------------------------------------------------
// Merged per-head RMSNorm + RoPE over BOTH Q and K, in-place.
// ---------------------------------------------------------------------------
__global__ void rms_rope_all(float* __restrict__ Qx, float* __restrict__ Kx,
                             const float* __restrict__ qw, const float* __restrict__ kw,
                             const float* __restrict__ cosp, const float* __restrict__ sinp) {
    const int NQ = S_LEN * NH;
    int warp = (blockIdx.x * blockDim.x + threadIdx.x) >> 5;
    int lane = threadIdx.x & 31;

    float* p;
    const float* w;
    int s;
    if (warp < NQ) {
        p = Qx + (size_t)warp * HD;
        w = qw;
        s = warp / NH;
    } else {
        int t = warp - NQ;
        p = Kx + (size_t)t * HD;
        w = kw;
        s = t / NKV;
    }

    float4 x = *(float4*)(p + lane * 4);

    float ss = x.x * x.x + x.y * x.y + x.z * x.z + x.w * x.w;
#pragma unroll
    for (int o = 16; o; o >>= 1) ss += __shfl_xor_sync(0xffffffffu, ss, o);
    float r = rsqrtf(ss * (1.0f / HD) + 1e-6f);

    float4 wv = *(const float4*)(w + lane * 4);
    x.x *= r * wv.x; x.y *= r * wv.y; x.z *= r * wv.z; x.w *= r * wv.w;

    float4 rot;
    rot.x = __shfl_xor_sync(0xffffffffu, x.x, 16);
    rot.y = __shfl_xor_sync(0xffffffffu, x.y, 16);
    rot.z = __shfl_xor_sync(0xffffffffu, x.z, 16);
    rot.w = __shfl_xor_sync(0xffffffffu, x.w, 16);
    float sgn = (lane < 16) ? -1.f : 1.f;

    float4 cv = *(const float4*)(cosp + (size_t)s * HD + lane * 4);
    float4 sv = *(const float4*)(sinp + (size_t)s * HD + lane * 4);

    float4 o;
    o.x = x.x * cv.x + sgn * rot.x * sv.x;
    o.y = x.y * cv.y + sgn * rot.y * sv.y;
    o.z = x.z * cv.z + sgn * rot.z * sv.z;
    o.w = x.w * cv.w + sgn * rot.w * sv.w;
    *(float4*)(p + lane * 4) = o;
}

// ---------------------------------------------------------------------------
// Tensor-core causal GQA flash attention (FA-2 style, TF32 mma).
// Block: 128 threads = 4 warps; block owns 64 q rows of one head.
// Warp strip: 16 rows, full 128-dim O accumulator in registers.
// Fixed-max softmax (scores bounded: |q|=|k|=sqrt(128) -> s*scale <= 11.33).
// Q split hi/lo (2 QK mma chains) to kill the q-side TF32 rounding error.
// Smem: Qs fp32 [64][132], Ks tf32 [64][132], Vs tf32 [64][136] = 100KB.
// ---------------------------------------------------------------------------
#define QS_STRIDE 132
#define VS_STRIDE 136

__global__ void __launch_bounds__(128) flash_tc(const float* __restrict__ Q,
                                                const float* __restrict__ K,
                                                const float* __restrict__ V,
                                                float* __restrict__ O) {
    extern __shared__ uint32_t smf[];
    float*    Qs = (float*)smf;               // [64][132] fp32
    uint32_t* Ks = smf + 64 * QS_STRIDE;      // [64][132] tf32
    uint32_t* Vs = smf + 2 * 64 * QS_STRIDE;  // [64][136] tf32

    const int tid  = threadIdx.x;
    const int w    = tid >> 5;
    const int lane = tid & 31;
    const int g    = lane >> 2;
    const int c    = lane & 3;
    const int h    = blockIdx.y;
    const int kvh  = h >> 2;
    const int base = blockIdx.x * 64;
    const int m0   = w * 16;
    const float scale = 0.08838834764831845f;  // 1/sqrt(128)
    const float FM = 12.0f;

    // stage Q tile (fp32)
    {
        int r = tid >> 1, half = (tid & 1) * 64;
        const float* src = Q + (size_t)(base + r) * QDIM + h * HD + half;
        float* dst = Qs + r * QS_STRIDE + half;
#pragma unroll
        for (int i = 0; i < 16; i++)
            *(float4*)(dst + i * 4) = *(const float4*)(src + i * 4);
    }

    float oacc[16][4];
#pragma unroll
    for (int i = 0; i < 16; i++) {
        oacc[i][0] = 0.f; oacc[i][1] = 0.f; oacc[i][2] = 0.f; oacc[i][3] = 0.f;
    }
    float lr0 = 0.f, lr1 = 0.f;

    const int row0 = base + m0 + g;
    const int row1 = row0 + 8;

    for (int kb = 0; kb <= base; kb += 64) {
        __syncthreads();
        // stage K, V (tf32)
        {
            int r = tid >> 1, half = (tid & 1) * 64;
            const float* ks = K + (size_t)(kb + r) * KVDIM + kvh * HD + half;
            const float* vs = V + (size_t)(kb + r) * KVDIM + kvh * HD + half;
            uint32_t* kd = Ks + r * QS_STRIDE + half;
            uint32_t* vd = Vs + r * VS_STRIDE + half;
#pragma unroll
            for (int i = 0; i < 16; i++) {
                float4 k4 = *(const float4*)(ks + i * 4);
                uint4 ku = {f2tf(k4.x), f2tf(k4.y), f2tf(k4.z), f2tf(k4.w)};
                *(uint4*)(kd + i * 4) = ku;
                float4 v4 = *(const float4*)(vs + i * 4);
                uint4 vu = {f2tf(v4.x), f2tf(v4.y), f2tf(v4.z), f2tf(v4.w)};
                *(uint4*)(vd + i * 4) = vu;
            }
        }
        __syncthreads();

        // ---- S = Q @ K^T  (warp strip 16x64), Q split hi/lo ----
        float sacc[8][4];
#pragma unroll
        for (int nt = 0; nt < 8; nt++) {
            sacc[nt][0] = 0.f; sacc[nt][1] = 0.f; sacc[nt][2] = 0.f; sacc[nt][3] = 0.f;
        }
#pragma unroll
        for (int ks8 = 0; ks8 < 16; ks8++) {
            const int kk = ks8 * 8;
            float q0 = Qs[(m0 + g) * QS_STRIDE + kk + c];
            float q1 = Qs[(m0 + 8 + g) * QS_STRIDE + kk + c];
            float q2 = Qs[(m0 + g) * QS_STRIDE + kk + c + 4];
            float q3 = Qs[(m0 + 8 + g) * QS_STRIDE + kk + c + 4];
            uint32_t ahi[4], alo[4];
            ahi[0] = f2tf(q0); alo[0] = f2tf(q0 - __uint_as_float(ahi[0]));
            ahi[1] = f2tf(q1); alo[1] = f2tf(q1 - __uint_as_float(ahi[1]));
            ahi[2] = f2tf(q2); alo[2] = f2tf(q2 - __uint_as_float(ahi[2]));
            ahi[3] = f2tf(q3); alo[3] = f2tf(q3 - __uint_as_float(ahi[3]));
#pragma unroll
            for (int nt = 0; nt < 8; nt++) {
                uint32_t b[2];
                b[0] = Ks[(nt * 8 + g) * QS_STRIDE + kk + c];
                b[1] = Ks[(nt * 8 + g) * QS_STRIDE + kk + c + 4];
                mma_tf32(sacc[nt], alo, b);
                mma_tf32(sacc[nt], ahi, b);
            }
        }

        // ---- softmax (fixed max), convert P to tf32 bits ----
        uint32_t pb[8][4];
#pragma unroll
        for (int nt = 0; nt < 8; nt++) {
            int colb = kb + nt * 8 + 2 * c;
            float p0 = (colb     <= row0) ? __expf(fmaf(sacc[nt][0], scale, -FM)) : 0.f;
            float p1 = (colb + 1 <= row0) ? __expf(fmaf(sacc[nt][1], scale, -FM)) : 0.f;
            float p2 = (colb     <= row1) ? __expf(fmaf(sacc[nt][2], scale, -FM)) : 0.f;
            float p3 = (colb + 1 <= row1) ? __expf(fmaf(sacc[nt][3], scale, -FM)) : 0.f;
            lr0 += p0 + p1;
            lr1 += p2 + p3;
            pb[nt][0] = f2tf(p0); pb[nt][1] = f2tf(p1);
            pb[nt][2] = f2tf(p2); pb[nt][3] = f2tf(p3);
        }

        // ---- O += P @ V ----
        const int src0 = (lane & ~3) | (c >> 1);
        const int src1 = src0 + 2;
#pragma unroll
        for (int kt = 0; kt < 8; kt++) {
            uint32_t x0 = __shfl_sync(0xffffffffu, pb[kt][0], src0);
            uint32_t x1 = __shfl_sync(0xffffffffu, pb[kt][1], src0);
            uint32_t x2 = __shfl_sync(0xffffffffu, pb[kt][2], src0);
            uint32_t x3 = __shfl_sync(0xffffffffu, pb[kt][3], src0);
            uint32_t y0 = __shfl_sync(0xffffffffu, pb[kt][0], src1);
            uint32_t y1 = __shfl_sync(0xffffffffu, pb[kt][1], src1);
            uint32_t y2 = __shfl_sync(0xffffffffu, pb[kt][2], src1);
            uint32_t y3 = __shfl_sync(0xffffffffu, pb[kt][3], src1);
            uint32_t a[4];
            a[0] = (c & 1) ? x1 : x0;   // P(g,   key kt*8+c)
            a[1] = (c & 1) ? x3 : x2;   // P(g+8, key kt*8+c)
            a[2] = (c & 1) ? y1 : y0;   // P(g,   key kt*8+c+4)
            a[3] = (c & 1) ? y3 : y2;   // P(g+8, key kt*8+c+4)
#pragma unroll
            for (int nt = 0; nt < 16; nt++) {
                uint32_t b[2];
                b[0] = Vs[(kt * 8 + c) * VS_STRIDE + nt * 8 + g];
                b[1] = Vs[(kt * 8 + c + 4) * VS_STRIDE + nt * 8 + g];
                mma_tf32(oacc[nt], a, b);
            }
        }
    }

    // ---- epilogue: reduce l across the 4 threads of each row, store ----
    lr0 += __shfl_xor_sync(0xffffffffu, lr0, 1);
    lr0 += __shfl_xor_sync(0xffffffffu, lr0, 2);
    lr1 += __shfl_xor_sync(0xffffffffu, lr1, 1);
    lr1 += __shfl_xor_sync(0xffffffffu, lr1, 2);
    float inv0 = 1.f / lr0;
    float inv1 = 1.f / lr1;

    float* o0 = O + (size_t)row0 * QDIM + h * HD;
    float* o1 = O + (size_t)row1 * QDIM + h * HD;
#pragma unroll
    for (int nt = 0; nt < 16; nt++) {
        int col = nt * 8 + 2 * c;
        float2 v0 = {oacc[nt][0] * inv0, oacc[nt][1] * inv0};
        float2 v1 = {oacc[nt][2] * inv1, oacc[nt][3] * inv1};
        *(float2*)(o0 + col) = v0;
        *(float2*)(o1 + col) = v1;
    }
}

// ---------------------------------------------------------------------------
extern "C" void kernel_launch(void* const* d_in, const int* in_sizes, int n_in,
                              void* d_out, int out_size) {
    const float* X    = (const float*)d_in[0];
    const float* cosp = (const float*)d_in[1];
    const float* sinp = (const float*)d_in[2];
    const float* Wq   = (const float*)d_in[3];
    const float* Wk   = (const float*)d_in[4];
    const float* Wv   = (const float*)d_in[5];
    const float* Wo   = (const float*)d_in[6];
    const float* qw   = (const float*)d_in[7];
    const float* kw   = (const float*)d_in[8];
    float* out = (float*)d_out;

    float *Q, *K, *V, *AO;
    cudaGetSymbolAddress((void**)&Q,  g_Q);
    cudaGetSymbolAddress((void**)&K,  g_K);
    cudaGetSymbolAddress((void**)&V,  g_V);
    cudaGetSymbolAddress((void**)&AO, g_AO);

    // Q projection
    tf32_gemm_nt<<<dim3(QDIM / 128, S_LEN / 128), 256>>>(X, Wq, Q, S_LEN, QDIM, HID);

    // K + V projections (merged launch)
    tf32_gemm_kv<<<dim3(KVDIM / 128, S_LEN / 128, 2), 256>>>(X, Wk, Wv, K, V, KVDIM, HID);

    // RMSNorm + RoPE on Q and K
    {
        int nwarps = S_LEN * NH + S_LEN * NKV;
        rms_rope_all<<<nwarps / 8, 256>>>(Q, K, qw, kw, cosp, sinp);
    }

    // Tensor-core flash attention
    int smem = (2 * 64 * QS_STRIDE + 64 * VS_STRIDE) * 4;  // 102400 B
    cudaFuncSetAttribute(flash_tc, cudaFuncAttributeMaxDynamicSharedMemorySize, smem);
    flash_tc<<<dim3(S_LEN / 64, NH), 128, smem>>>(Q, K, V, AO);

    // Output projection
    tf32_gemm_nt<<<dim3(HID / 128, S_LEN / 128), 256>>>(AO, Wo, out, S_LEN, HID, QDIM);
}

// round 10
// speedup vs baseline: 5.2146x; 1.1262x over previous
#include <cuda_runtime.h>
#include <math.h>
#include <stdint.h>

#define S_LEN 2048
#define HID   2560
#define NH    32
#define NKV   8
#define HD    128
#define QDIM  (NH*HD)    // 4096
#define KVDIM (NKV*HD)   // 1024

// Scratch (static device arrays; no allocation allowed)
__device__ float g_Q [S_LEN*QDIM];
__device__ float g_K [S_LEN*KVDIM];
__device__ float g_V [S_LEN*KVDIM];
__device__ float g_AO[S_LEN*QDIM];

// ---------------------------------------------------------------------------
// helpers
// ---------------------------------------------------------------------------
__device__ __forceinline__ uint32_t f2tf(float x) {
    uint32_t y;
    asm("cvt.rna.tf32.f32 %0, %1;" : "=r"(y) : "f"(x));
    return y;
}

__device__ __forceinline__ void mma_tf32(float* d, const uint32_t* a, const uint32_t* b) {
    asm volatile(
        "mma.sync.aligned.m16n8k8.row.col.f32.tf32.tf32.f32 "
        "{%0,%1,%2,%3}, {%4,%5,%6,%7}, {%8,%9}, {%0,%1,%2,%3};\n"
        : "+f"(d[0]), "+f"(d[1]), "+f"(d[2]), "+f"(d[3])
        : "r"(a[0]), "r"(a[1]), "r"(a[2]), "r"(a[3]), "r"(b[0]), "r"(b[1]));
}

// ---------------------------------------------------------------------------
// TF32 tensor-core GEMM NT body: C[M,N] = A[M,K] * B[N,K]^T
// BM=BN=128, BK=16, 256 threads (8 warps, 2x4), warp tile 64x32.
// Double-buffered smem (ping-pong), one sync per K-tile.
// ---------------------------------------------------------------------------
#define SMS 20  // smem row stride in words

__device__ __forceinline__ void gemm_body(const float* __restrict__ A,
                                          const float* __restrict__ B,
                                          float* __restrict__ C,
                                          int N, int Kd, int bx, int by,
                                          uint32_t* As, uint32_t* Bs) {
    const int tid  = threadIdx.x;
    const int wid  = tid >> 5;
    const int lane = tid & 31;
    const int wm   = (wid & 1) * 64;
    const int wn   = (wid >> 1) * 32;
    const int g    = lane >> 2;
    const int c    = lane & 3;

    const int sr = tid >> 2;
    const int sc = (tid & 3) * 4;
    const float* Ap = A + (size_t)(by * 128 + sr) * Kd + sc;
    const float* Bp = B + (size_t)(bx * 128 + sr) * Kd + sc;

    float acc[4][4][4];
#pragma unroll
    for (int i = 0; i < 4; i++)
#pragma unroll
        for (int j = 0; j < 4; j++)
#pragma unroll
            for (int k = 0; k < 4; k++) acc[i][j][k] = 0.f;

    float4 ra0 = *(const float4*)(Ap);
    float4 ra1 = *(const float4*)(Ap + (size_t)64 * Kd);
    float4 rb0 = *(const float4*)(Bp);
    float4 rb1 = *(const float4*)(Bp + (size_t)64 * Kd);

    {
        uint4 u;
        u.x = f2tf(ra0.x); u.y = f2tf(ra0.y); u.z = f2tf(ra0.z); u.w = f2tf(ra0.w);
        *(uint4*)&As[sr * SMS + sc] = u;
        u.x = f2tf(ra1.x); u.y = f2tf(ra1.y); u.z = f2tf(ra1.z); u.w = f2tf(ra1.w);
        *(uint4*)&As[(sr + 64) * SMS + sc] = u;
        u.x = f2tf(rb0.x); u.y = f2tf(rb0.y); u.z = f2tf(rb0.z); u.w = f2tf(rb0.w);
        *(uint4*)&Bs[sr * SMS + sc] = u;
        u.x = f2tf(rb1.x); u.y = f2tf(rb1.y); u.z = f2tf(rb1.z); u.w = f2tf(rb1.w);
        *(uint4*)&Bs[(sr + 64) * SMS + sc] = u;
    }
    __syncthreads();

    int cur = 0;
    for (int k0 = 0; k0 < Kd; k0 += 16) {
        const bool has_next = (k0 + 16 < Kd);
        if (has_next) {
            ra0 = *(const float4*)(Ap + k0 + 16);
            ra1 = *(const float4*)(Ap + (size_t)64 * Kd + k0 + 16);
            rb0 = *(const float4*)(Bp + k0 + 16);
            rb1 = *(const float4*)(Bp + (size_t)64 * Kd + k0 + 16);
        }

        const uint32_t* Ab = As + cur * (128 * SMS * 2);
        const uint32_t* Bb = Bs + cur * (128 * SMS * 2);
#pragma unroll
        for (int kk = 0; kk < 16; kk += 8) {
            uint32_t af[4][4], bf[4][2];
#pragma unroll
            for (int mt = 0; mt < 4; mt++) {
                int r0 = wm + mt * 16 + g;
                af[mt][0] = Ab[r0 * SMS + kk + c];
                af[mt][1] = Ab[(r0 + 8) * SMS + kk + c];
                af[mt][2] = Ab[r0 * SMS + kk + c + 4];
                af[mt][3] = Ab[(r0 + 8) * SMS + kk + c + 4];
            }
#pragma unroll
            for (int nt = 0; nt < 4; nt++) {
                int n0 = wn + nt * 8 + g;
                bf[nt][0] = Bb[n0 * SMS + kk + c];
                bf[nt][1] = Bb[n0 * SMS + kk + c + 4];
            }
#pragma unroll
            for (int mt = 0; mt < 4; mt++)
#pragma unroll
                for (int nt = 0; nt < 4; nt++)
                    mma_tf32(acc[mt][nt], af[mt], bf[nt]);
        }

        if (has_next) {
            uint32_t* An = As + (cur ^ 1) * (128 * SMS * 2);
            uint32_t* Bn = Bs + (cur ^ 1) * (128 * SMS * 2);
            uint4 u;
            u.x = f2tf(ra0.x); u.y = f2tf(ra0.y); u.z = f2tf(ra0.z); u.w = f2tf(ra0.w);
            *(uint4*)&An[sr * SMS + sc] = u;
            u.x = f2tf(ra1.x); u.y = f2tf(ra1.y); u.z = f2tf(ra1.z); u.w = f2tf(ra1.w);
            *(uint4*)&An[(sr + 64) * SMS + sc] = u;
            u.x = f2tf(rb0.x); u.y = f2tf(rb0.y); u.z = f2tf(rb0.z); u.w = f2tf(rb0.w);
            *(uint4*)&Bn[sr * SMS + sc] = u;
            u.x = f2tf(rb1.x); u.y = f2tf(rb1.y); u.z = f2tf(rb1.z); u.w = f2tf(rb1.w);
            *(uint4*)&Bn[(sr + 64) * SMS + sc] = u;
            __syncthreads();
            cur ^= 1;
        }
    }

#pragma unroll
    for (int mt = 0; mt < 4; mt++) {
#pragma unroll
        for (int nt = 0; nt < 4; nt++) {
            int row = by * 128 + wm + mt * 16 + g;
            int col = bx * 128 + wn + nt * 8 + c * 2;
            float2 v0 = {acc[mt][nt][0], acc[mt][nt][1]};
            float2 v1 = {acc[mt][nt][2], acc[mt][nt][3]};
            *(float2*)(C + (size_t)row * N + col)       = v0;
            *(float2*)(C + (size_t)(row + 8) * N + col) = v1;
        }
    }
}

// Q, K, V projections merged into one launch (blockIdx.z selects).
// z=0: Q (all 32 x-blocks), z=1: K (x<8), z=2: V (x<8).
__global__ void __launch_bounds__(256, 2) tf32_gemm_qkv(const float* __restrict__ A,
                                                        const float* __restrict__ Bq,
                                                        const float* __restrict__ Bk,
                                                        const float* __restrict__ Bv,
                                                        float* __restrict__ Cq,
                                                        float* __restrict__ Ck,
                                                        float* __restrict__ Cv,
                                                        int Kd) {
    __shared__ uint32_t As[2 * 128 * SMS * 2];
    __shared__ uint32_t Bs[2 * 128 * SMS * 2];
    const int z = blockIdx.z;
    if (z == 0) {
        gemm_body(A, Bq, Cq, QDIM, Kd, blockIdx.x, blockIdx.y, As, Bs);
    } else {
        if (blockIdx.x >= KVDIM / 128) return;
        if (z == 1) gemm_body(A, Bk, Ck, KVDIM, Kd, blockIdx.x, blockIdx.y, As, Bs);
        else        gemm_body(A, Bv, Cv, KVDIM, Kd, blockIdx.x, blockIdx.y, As, Bs);
    }
}

__global__ void __launch_bounds__(256, 2) tf32_gemm_nt(const float* __restrict__ A,
                                                       const float* __restrict__ B,
                                                       float* __restrict__ C,
                                                       int M, int N, int Kd) {
    __shared__ uint32_t As[2 * 128 * SMS * 2];
    __shared__ uint32_t Bs[2 * 128 * SMS * 2];
    gemm_body(A, B, C, N, Kd, blockIdx.x, blockIdx.y, As, Bs);
}

// ---------------------------------------------------------------------------
// Merged per-head RMSNorm + RoPE over BOTH Q and K, in-place.
// ---------------------------------------------------------------------------
__global__ void rms_rope_all(float* __restrict__ Qx, float* __restrict__ Kx,
                             const float* __restrict__ qw, const float* __restrict__ kw,
                             const float* __restrict__ cosp, const float* __restrict__ sinp) {
    const int NQ = S_LEN * NH;
    int warp = (blockIdx.x * blockDim.x + threadIdx.x) >> 5;
    int lane = threadIdx.x & 31;

    float* p;
    const float* w;
    int s;
    if (warp < NQ) {
        p = Qx + (size_t)warp * HD;
        w = qw;
        s = warp / NH;
    } else {
        int t = warp - NQ;
        p = Kx + (size_t)t * HD;
        w = kw;
        s = t / NKV;
    }

    float4 x = *(float4*)(p + lane * 4);

    float ss = x.x * x.x + x.y * x.y + x.z * x.z + x.w * x.w;
#pragma unroll
    for (int o = 16; o; o >>= 1) ss += __shfl_xor_sync(0xffffffffu, ss, o);
    float r = rsqrtf(ss * (1.0f / HD) + 1e-6f);

    float4 wv = *(const float4*)(w + lane * 4);
    x.x *= r * wv.x; x.y *= r * wv.y; x.z *= r * wv.z; x.w *= r * wv.w;

    float4 rot;
    rot.x = __shfl_xor_sync(0xffffffffu, x.x, 16);
    rot.y = __shfl_xor_sync(0xffffffffu, x.y, 16);
    rot.z = __shfl_xor_sync(0xffffffffu, x.z, 16);
    rot.w = __shfl_xor_sync(0xffffffffu, x.w, 16);
    float sgn = (lane < 16) ? -1.f : 1.f;

    float4 cv = *(const float4*)(cosp + (size_t)s * HD + lane * 4);
    float4 sv = *(const float4*)(sinp + (size_t)s * HD + lane * 4);

    float4 o;
    o.x = x.x * cv.x + sgn * rot.x * sv.x;
    o.y = x.y * cv.y + sgn * rot.y * sv.y;
    o.z = x.z * cv.z + sgn * rot.z * sv.z;
    o.w = x.w * cv.w + sgn * rot.w * sv.w;
    *(float4*)(p + lane * 4) = o;
}

// ---------------------------------------------------------------------------
// Tensor-core causal GQA flash attention (FA-2 style, TF32 mma).
// Block: 256 threads = 8 warps; block owns 128 q rows of one head.
// Warp strip: 16 rows, full 128-dim O accumulator in registers.
// Fixed-max softmax (scores bounded: |q|=|k|=sqrt(128) -> s*scale <= 11.33).
// Q hi/lo split PRECOMPUTED into smem once per block (2 QK mma chains).
// Smem: Qhi[128][132] + Qlo[128][132] + Ks[64][132] + Vs[64][136] ~= 204KB.
// ---------------------------------------------------------------------------
#define QS_STRIDE 132
#define VS_STRIDE 136

__global__ void __launch_bounds__(256, 1) flash_tc(const float* __restrict__ Q,
                                                   const float* __restrict__ K,
                                                   const float* __restrict__ V,
                                                   float* __restrict__ O) {
    extern __shared__ uint32_t smf[];
    uint32_t* Qhi = smf;                                // [128][132] tf32
    uint32_t* Qlo = smf + 128 * QS_STRIDE;              // [128][132] tf32
    uint32_t* Ks  = smf + 2 * 128 * QS_STRIDE;          // [64][132] tf32
    uint32_t* Vs  = Ks + 64 * QS_STRIDE;                // [64][136] tf32

    const int tid  = threadIdx.x;
    const int w    = tid >> 5;
    const int lane = tid & 31;
    const int g    = lane >> 2;
    const int c    = lane & 3;
    const int h    = blockIdx.y;
    const int kvh  = h >> 2;
    const int base = blockIdx.x * 128;
    const int m0   = w * 16;
    const float scale = 0.08838834764831845f;  // 1/sqrt(128)
    const float FM = 12.0f;

    // stage Q tile with hi/lo split (once per block)
    {
        int r = tid >> 1, half = (tid & 1) * 64;
        const float* src = Q + (size_t)(base + r) * QDIM + h * HD + half;
        uint32_t* dh = Qhi + r * QS_STRIDE + half;
        uint32_t* dl = Qlo + r * QS_STRIDE + half;
#pragma unroll
        for (int i = 0; i < 16; i++) {
            float4 q4 = *(const float4*)(src + i * 4);
            uint4 hv, lv;
            hv.x = f2tf(q4.x); lv.x = f2tf(q4.x - __uint_as_float(hv.x));
            hv.y = f2tf(q4.y); lv.y = f2tf(q4.y - __uint_as_float(hv.y));
            hv.z = f2tf(q4.z); lv.z = f2tf(q4.z - __uint_as_float(hv.z));
            hv.w = f2tf(q4.w); lv.w = f2tf(q4.w - __uint_as_float(hv.w));
            *(uint4*)(dh + i * 4) = hv;
            *(uint4*)(dl + i * 4) = lv;
        }
    }

    float oacc[16][4];
#pragma unroll
    for (int i = 0; i < 16; i++) {
        oacc[i][0] = 0.f; oacc[i][1] = 0.f; oacc[i][2] = 0.f; oacc[i][3] = 0.f;
    }
    float lr0 = 0.f, lr1 = 0.f;

    const int row0 = base + m0 + g;
    const int row1 = row0 + 8;
    const int wmax = base + m0 + 15;   // last q row of this warp's strip

    for (int kb = 0; kb <= base + 127; kb += 64) {
        __syncthreads();   // Q staging (first iter) / previous compute done
        // stage K, V (tf32)
        {
            int r = tid >> 2, qtr = (tid & 3) * 32;
            const float* ks = K + (size_t)(kb + r) * KVDIM + kvh * HD + qtr;
            const float* vs = V + (size_t)(kb + r) * KVDIM + kvh * HD + qtr;
            uint32_t* kd = Ks + r * QS_STRIDE + qtr;
            uint32_t* vd = Vs + r * VS_STRIDE + qtr;
#pragma unroll
            for (int i = 0; i < 8; i++) {
                float4 k4 = *(const float4*)(ks + i * 4);
                uint4 ku = {f2tf(k4.x), f2tf(k4.y), f2tf(k4.z), f2tf(k4.w)};
                *(uint4*)(kd + i * 4) = ku;
                float4 v4 = *(const float4*)(vs + i * 4);
                uint4 vu = {f2tf(v4.x), f2tf(v4.y), f2tf(v4.z), f2tf(v4.w)};
                *(uint4*)(vd + i * 4) = vu;
            }
        }
        __syncthreads();

        if (kb > wmax) continue;   // whole tile causally masked for this warp

        // ---- S = Q @ K^T  (warp strip 16x64), Q hi/lo from smem ----
        float sacc[8][4];
#pragma unroll
        for (int nt = 0; nt < 8; nt++) {
            sacc[nt][0] = 0.f; sacc[nt][1] = 0.f; sacc[nt][2] = 0.f; sacc[nt][3] = 0.f;
        }
#pragma unroll
        for (int ks8 = 0; ks8 < 16; ks8++) {
            const int kk = ks8 * 8;
            uint32_t ahi[4], alo[4];
            ahi[0] = Qhi[(m0 + g) * QS_STRIDE + kk + c];
            ahi[1] = Qhi[(m0 + 8 + g) * QS_STRIDE + kk + c];
            ahi[2] = Qhi[(m0 + g) * QS_STRIDE + kk + c + 4];
            ahi[3] = Qhi[(m0 + 8 + g) * QS_STRIDE + kk + c + 4];
            alo[0] = Qlo[(m0 + g) * QS_STRIDE + kk + c];
            alo[1] = Qlo[(m0 + 8 + g) * QS_STRIDE + kk + c];
            alo[2] = Qlo[(m0 + g) * QS_STRIDE + kk + c + 4];
            alo[3] = Qlo[(m0 + 8 + g) * QS_STRIDE + kk + c + 4];
#pragma unroll
            for (int nt = 0; nt < 8; nt++) {
                uint32_t b[2];
                b[0] = Ks[(nt * 8 + g) * QS_STRIDE + kk + c];
                b[1] = Ks[(nt * 8 + g) * QS_STRIDE + kk + c + 4];
                mma_tf32(sacc[nt], alo, b);
                mma_tf32(sacc[nt], ahi, b);
            }
        }

        // ---- softmax (fixed max), convert P to tf32 bits ----
        uint32_t pb[8][4];
#pragma unroll
        for (int nt = 0; nt < 8; nt++) {
            int colb = kb + nt * 8 + 2 * c;
            float p0 = (colb     <= row0) ? __expf(fmaf(sacc[nt][0], scale, -FM)) : 0.f;
            float p1 = (colb + 1 <= row0) ? __expf(fmaf(sacc[nt][1], scale, -FM)) : 0.f;
            float p2 = (colb     <= row1) ? __expf(fmaf(sacc[nt][2], scale, -FM)) : 0.f;
            float p3 = (colb + 1 <= row1) ? __expf(fmaf(sacc[nt][3], scale, -FM)) : 0.f;
            lr0 += p0 + p1;
            lr1 += p2 + p3;
            pb[nt][0] = f2tf(p0); pb[nt][1] = f2tf(p1);
            pb[nt][2] = f2tf(p2); pb[nt][3] = f2tf(p3);
        }

        // ---- O += P @ V ----
        const int src0 = (lane & ~3) | (c >> 1);
        const int src1 = src0 + 2;
#pragma unroll
        for (int kt = 0; kt < 8; kt++) {
            uint32_t x0 = __shfl_sync(0xffffffffu, pb[kt][0], src0);
            uint32_t x1 = __shfl_sync(0xffffffffu, pb[kt][1], src0);
            uint32_t x2 = __shfl_sync(0xffffffffu, pb[kt][2], src0);
            uint32_t x3 = __shfl_sync(0xffffffffu, pb[kt][3], src0);
            uint32_t y0 = __shfl_sync(0xffffffffu, pb[kt][0], src1);
            uint32_t y1 = __shfl_sync(0xffffffffu, pb[kt][1], src1);
            uint32_t y2 = __shfl_sync(0xffffffffu, pb[kt][2], src1);
            uint32_t y3 = __shfl_sync(0xffffffffu, pb[kt][3], src1);
            uint32_t a[4];
            a[0] = (c & 1) ? x1 : x0;   // P(g,   key kt*8+c)
            a[1] = (c & 1) ? x3 : x2;   // P(g+8, key kt*8+c)
            a[2] = (c & 1) ? y1 : y0;   // P(g,   key kt*8+c+4)
            a[3] = (c & 1) ? y3 : y2;   // P(g+8, key kt*8+c+4)
#pragma unroll
            for (int nt = 0; nt < 16; nt++) {
                uint32_t b[2];
                b[0] = Vs[(kt * 8 + c) * VS_STRIDE + nt * 8 + g];
                b[1] = Vs[(kt * 8 + c + 4) * VS_STRIDE + nt * 8 + g];
                mma_tf32(oacc[nt], a, b);
            }
        }
    }

    // ---- epilogue: reduce l across the 4 threads of each row, store ----
    lr0 += __shfl_xor_sync(0xffffffffu, lr0, 1);
    lr0 += __shfl_xor_sync(0xffffffffu, lr0, 2);
    lr1 += __shfl_xor_sync(0xffffffffu, lr1, 1);
    lr1 += __shfl_xor_sync(0xffffffffu, lr1, 2);
    float inv0 = 1.f / lr0;
    float inv1 = 1.f / lr1;

    float* o0 = O + (size_t)row0 * QDIM + h * HD;
    float* o1 = O + (size_t)row1 * QDIM + h * HD;
#pragma unroll
    for (int nt = 0; nt < 16; nt++) {
        int col = nt * 8 + 2 * c;
        float2 v0 = {oacc[nt][0] * inv0, oacc[nt][1] * inv0};
        float2 v1 = {oacc[nt][2] * inv1, oacc[nt][3] * inv1};
        *(float2*)(o0 + col) = v0;
        *(float2*)(o1 + col) = v1;
    }
}

// ---------------------------------------------------------------------------
extern "C" void kernel_launch(void* const* d_in, const int* in_sizes, int n_in,
                              void* d_out, int out_size) {
    const float* X    = (const float*)d_in[0];
    const float* cosp = (const float*)d_in[1];
    const float* sinp = (const float*)d_in[2];
    const float* Wq   = (const float*)d_in[3];
    const float* Wk   = (const float*)d_in[4];
    const float* Wv   = (const float*)d_in[5];
    const float* Wo   = (const float*)d_in[6];
    const float* qw   = (const float*)d_in[7];
    const float* kw   = (const float*)d_in[8];
    float* out = (float*)d_out;

    float *Q, *K, *V, *AO;
    cudaGetSymbolAddress((void**)&Q,  g_Q);
    cudaGetSymbolAddress((void**)&K,  g_K);
    cudaGetSymbolAddress((void**)&V,  g_V);
    cudaGetSymbolAddress((void**)&AO, g_AO);

    // Q + K + V projections in one launch
    tf32_gemm_qkv<<<dim3(QDIM / 128, S_LEN / 128, 3), 256>>>(X, Wq, Wk, Wv, Q, K, V, HID);

    // RMSNorm + RoPE on Q and K
    {
        int nwarps = S_LEN * NH + S_LEN * NKV;
        rms_rope_all<<<nwarps / 8, 256>>>(Q, K, qw, kw, cosp, sinp);
    }

    // Tensor-core flash attention (8 warps, 128 q-rows/block)
    int smem = (2 * 128 * QS_STRIDE + 64 * QS_STRIDE + 64 * VS_STRIDE) * 4;  // ~204KB
    cudaFuncSetAttribute(flash_tc, cudaFuncAttributeMaxDynamicSharedMemorySize, smem);
    flash_tc<<<dim3(S_LEN / 128, NH), 256, smem>>>(Q, K, V, AO);

    // Output projection
    tf32_gemm_nt<<<dim3(HID / 128, S_LEN / 128), 256>>>(AO, Wo, out, S_LEN, HID, QDIM);
}